// round 14
// baseline (speedup 1.0000x reference)
#include <cuda_runtime.h>
#include <math.h>
#include <stdint.h>

// Problem constants (fixed shapes)
#define BN 2048
#define ZD 512
#define HD 384
#define TN 32
#define G4 (4*HD)              // 1536
#define OUT_STRIDE (TN*ZD)     // 16384
#define E_STRIDE ((TN-1)*ZD)   // 15872
#define HC_STRIDE (2*HD)       // 768
#define SEQ ((TN-1)*BN)        // 63488

#define LDS 36                 // smem row stride in words (32 + 4 pad)

// Scratch (allocation-free: __device__ globals)
__device__ float g_h0[(size_t)BN*HD];
__device__ float g_h1[(size_t)BN*HD];
__device__ float g_c[(size_t)BN*HD];
__device__ float g_hc[(size_t)SEQ*HC_STRIDE];
__device__ float g_mid[(size_t)SEQ*ZD];
__device__ float g_outTf[(size_t)BN*ZD];
__device__ float g_WihEnc_t[(size_t)G4*ZD];
__device__ float g_Wih_t[(size_t)G4*ZD];
__device__ float g_Whh_t[(size_t)G4*HD];
__device__ float g_bsumEnc[G4];
__device__ float g_bsum[G4];
__device__ float g_fc1_t[(size_t)ZD*HC_STRIDE];
__device__ float g_fc2_t[(size_t)ZD*ZD];
__device__ float g_wT[(size_t)ZD*HD];

__device__ __forceinline__ float sigf(float x) { return 1.0f / (1.0f + __expf(-x)); }

__device__ __forceinline__ uint32_t f2tf(float x) {
    uint32_t r;
    asm("cvt.rna.tf32.f32 %0, %1;" : "=r"(r) : "f"(x));
    return r;
}
__device__ __forceinline__ float rtf(float x) { return __uint_as_float(f2tf(x)); }

__device__ __forceinline__ uint32_t smem_u32(const void* p) {
    uint32_t a;
    asm("{ .reg .u64 t; cvta.to.shared.u64 t, %1; cvt.u32.u64 %0, t; }" : "=r"(a) : "l"(p));
    return a;
}

__device__ __forceinline__ void mma_tf32(
    float* c, uint32_t a0, uint32_t a1, uint32_t a2, uint32_t a3,
    uint32_t b0, uint32_t b1)
{
    asm volatile(
        "mma.sync.aligned.m16n8k8.row.col.f32.tf32.tf32.f32 "
        "{%0,%1,%2,%3}, {%4,%5,%6,%7}, {%8,%9}, {%0,%1,%2,%3};"
        : "+f"(c[0]), "+f"(c[1]), "+f"(c[2]), "+f"(c[3])
        : "r"(a0), "r"(a1), "r"(a2), "r"(a3), "r"(b0), "r"(b1));
}

__device__ __forceinline__ void ldm4(uint32_t* r, uint32_t addr) {
    asm volatile("ldmatrix.sync.aligned.m8n8.x4.shared.b16 {%0,%1,%2,%3}, [%4];"
        : "=r"(r[0]), "=r"(r[1]), "=r"(r[2]), "=r"(r[3]) : "r"(addr));
}

__device__ __forceinline__ void cpa16(uint32_t dst, const void* src) {
    asm volatile("cp.async.ca.shared.global [%0], [%1], 16;" :: "r"(dst), "l"(src));
}

// Issue cp.async for a [ROWS x 32 floats] K-major tile (row stride LDS words).
template<int ROWS>
__device__ __forceinline__ void issue_tile(
    const float* __restrict__ G, int row0, int ld, int k0, uint32_t smemBase, int tid)
{
#pragma unroll
    for (int s = tid; s < ROWS * 8; s += 256) {
        const int row = s >> 3, c4 = s & 7;
        cpa16(smemBase + (uint32_t)(row * LDS + c4 * 4) * 4u,
              G + (size_t)(row0 + row) * ld + k0 + c4 * 4);
    }
}

// ---------------------------------------------------------------------------
// GEMM mainloop: tf32 mma.sync, NT, 3-stage cp.async ring, ldmatrix frags.
// 256 thr = 8 warps (4m x 2n). Tile 128 x (NF*16), K chunk 32, dual-A.
// Fills acc; caller owns the epilogue. MMA order identical to 2-stage version.
// ---------------------------------------------------------------------------
template<int NF>
__device__ __forceinline__ void run_gemm(
    float (&acc)[2][NF][4],
    const float* __restrict__ A1, int lda1, int K1,
    const float* __restrict__ A2, int lda2, int K2,
    const float* __restrict__ B1, int ldb1,
    const float* __restrict__ B2, int ldb2,
    int bm, int bn, uint32_t smBase)
{
    constexpr int BROWS = NF * 16;
    constexpr int AW    = 128 * LDS;
    constexpr int TILEW = (128 + BROWS) * LDS;

    const int tid = threadIdx.x;
    const int wid = tid >> 5, lane = tid & 31;
    const int wm  = (wid >> 1) * 32;
    const int wn  = (wid & 1) * (NF * 8);

#pragma unroll
    for (int mi = 0; mi < 2; mi++)
#pragma unroll
        for (int ni = 0; ni < NF; ni++)
#pragma unroll
            for (int j = 0; j < 4; j++) acc[mi][ni][j] = 0.0f;

    const int nch1 = K1 >> 5;
    const int nch  = nch1 + (K2 >> 5);

    auto chunkSrc = [&](int c, const float*& Ap, const float*& Bp,
                        int& la, int& lb, int& k0) {
        if (c < nch1) { Ap = A1; Bp = B1; la = lda1; lb = ldb1; k0 = c << 5; }
        else          { Ap = A2; Bp = B2; la = lda2; lb = ldb2; k0 = (c - nch1) << 5; }
    };
    auto issueChunk = [&](int c) {
        const float *Ap, *Bp; int la, lb, k0;
        chunkSrc(c, Ap, Bp, la, lb, k0);
        const uint32_t nb = smBase + (uint32_t)(c % 3) * TILEW * 4u;
        issue_tile<128>(Ap, bm, la, k0, nb, tid);
        issue_tile<BROWS>(Bp, bn, lb, k0, nb + AW * 4, tid);
        asm volatile("cp.async.commit_group;" ::: "memory");
    };

    const int a_r = (lane & 7) + ((lane >> 3) & 1) * 8;
    const int a_c = ((lane >> 4) & 1) * 4;
    const int b_r = ((lane >> 4) & 1) * 8 + (lane & 7);
    const int b_c = ((lane >> 3) & 1) * 4;
    const uint32_t aOfs0 = (uint32_t)((wm + a_r) * LDS + a_c) * 4u;
    const uint32_t aOfs1 = aOfs0 + 16u * LDS * 4u;
    const uint32_t bOfs  = (uint32_t)(AW + (wn + b_r) * LDS + b_c) * 4u;

    // prologue: prefetch chunks 0 and 1
    issueChunk(0);
    if (nch > 1) issueChunk(1);

#pragma unroll 1
    for (int c = 0; c < nch; ++c) {
        const uint32_t pb = smBase + (uint32_t)(c % 3) * TILEW * 4u;
        const int rem = nch - 1 - c;
        if (rem >= 2) {
            issueChunk(c + 2);
            asm volatile("cp.async.wait_group 2;" ::: "memory");
        } else if (rem == 1) {
            asm volatile("cp.async.wait_group 1;" ::: "memory");
        } else {
            asm volatile("cp.async.wait_group 0;" ::: "memory");
        }
        __syncthreads();
#pragma unroll
        for (int s = 0; s < 4; s++) {
            uint32_t a[2][4], bf[NF][2];
            ldm4(a[0], pb + aOfs0 + s * 32);
            ldm4(a[1], pb + aOfs1 + s * 32);
#pragma unroll
            for (int j = 0; j < NF / 2; j++) {
                uint32_t t[4];
                ldm4(t, pb + bOfs + (uint32_t)j * (16u * LDS * 4u) + s * 32);
                bf[2*j][0]   = t[0]; bf[2*j][1]   = t[1];
                bf[2*j+1][0] = t[2]; bf[2*j+1][1] = t[3];
            }
#pragma unroll
            for (int mi = 0; mi < 2; mi++)
#pragma unroll
                for (int ni = 0; ni < NF; ni++)
                    mma_tf32(acc[mi][ni], a[mi][0], a[mi][1], a[mi][2], a[mi][3],
                             bf[ni][0], bf[ni][1]);
        }
        __syncthreads();   // compute(c) done before iter c+1 refills buffer (c+3)%3
    }
}

// ---------------------------------------------------------------------------
// Fused gates GEMM + LSTM cell kernel (NF=12, gate-interleave-permuted weights).
// col P = 96*Wg + 8*(4v+g) + 2t + b  <->  unit j = 24*Wg + 6t + 3b + v.
// ---------------------------------------------------------------------------
__global__ __launch_bounds__(256) void gates_kernel(
    const float* __restrict__ A1, const float* __restrict__ A2,
    const float* __restrict__ B1, const float* __restrict__ B2,
    const float* __restrict__ bias,
    float* __restrict__ hOut, float* __restrict__ cPtr,
    int useC, float* __restrict__ hcRow, int hcStride)
{
    extern __shared__ uint32_t sm[];
    const uint32_t smBase = smem_u32(sm);
    const int tid = threadIdx.x;
    const int wid = tid >> 5, lane = tid & 31;
    const int grp = lane >> 2, tig = lane & 3;
    const int wm  = (wid >> 1) * 32;
    const int bm  = blockIdx.y * 128;
    const int bx  = blockIdx.x;

    float acc[2][12][4];
    run_gemm<12>(acc, A1, ZD, ZD, A2, HD, (A2 ? HD : 0),
                 B1, ZD, B2, HD, bm, bx * 192, smBase);

    const int Wg = bx * 2 + (wid & 1);
    const int jbase = 24 * Wg + 6 * tig;
    float bs[2][3][4];
    const float* bp = bias + 96 * Wg + 2 * tig;
#pragma unroll
    for (int b2 = 0; b2 < 2; b2++)
#pragma unroll
        for (int v = 0; v < 3; v++)
#pragma unroll
            for (int g = 0; g < 4; g++)
                bs[b2][v][g] = bp[8 * (4 * v + g) + b2];
#pragma unroll
    for (int mi = 0; mi < 2; mi++) {
#pragma unroll
        for (int rr = 0; rr < 2; rr++) {
            const int R = bm + wm + mi * 16 + grp + rr * 8;
#pragma unroll
            for (int b2 = 0; b2 < 2; b2++) {
#pragma unroll
                for (int v = 0; v < 3; v++) {
                    const float gi = acc[mi][4*v+0][rr*2+b2] + bs[b2][v][0];
                    const float gf = acc[mi][4*v+1][rr*2+b2] + bs[b2][v][1];
                    const float gg = acc[mi][4*v+2][rr*2+b2] + bs[b2][v][2];
                    const float go = acc[mi][4*v+3][rr*2+b2] + bs[b2][v][3];
                    const int j = jbase + 3 * b2 + v;
                    float cn = sigf(gi) * tanhf(gg);
                    if (useC) cn += sigf(gf) * cPtr[(size_t)R * HD + j];
                    const float hn = sigf(go) * tanhf(cn);
                    cPtr[(size_t)R * HD + j] = cn;
                    hOut[(size_t)R * HD + j] = rtf(hn);
                    if (hcRow) {
                        hcRow[(size_t)R * hcStride + j]      = rtf(hn);
                        hcRow[(size_t)R * hcStride + HD + j] = rtf(cn);
                    }
                }
            }
        }
    }
}

// ---------------------------------------------------------------------------
// mul kernel (NF=4): out = outPrev + 0.2*tanh(acc+bias); writes out (exact),
// e (exact, optional), outTf (tf32-rounded).
// ---------------------------------------------------------------------------
__global__ __launch_bounds__(256) void mul_kernel(
    const float* __restrict__ H, const float* __restrict__ W,
    const float* __restrict__ bias,
    float* __restrict__ C, const float* __restrict__ outPrev,
    float* __restrict__ ePtr, float* __restrict__ tfPtr)
{
    extern __shared__ uint32_t sm[];
    const uint32_t smBase = smem_u32(sm);
    const int tid = threadIdx.x;
    const int wid = tid >> 5, lane = tid & 31;
    const int grp = lane >> 2, tig = lane & 3;
    const int wm  = (wid >> 1) * 32;
    const int wn  = (wid & 1) * 32;
    const int bm  = blockIdx.y * 128;
    const int bn  = blockIdx.x * 64;

    float acc[2][4][4];
    run_gemm<4>(acc, H, HD, HD, nullptr, 0, 0, W, HD, nullptr, 0, bm, bn, smBase);

#pragma unroll
    for (int mi = 0; mi < 2; mi++) {
        const int r0 = bm + wm + mi * 16 + grp;
#pragma unroll
        for (int ni = 0; ni < 4; ni++) {
            const int col = bn + wn + ni * 8 + 2 * tig;
#pragma unroll
            for (int rr = 0; rr < 2; rr++) {
                const int row = r0 + rr * 8;
                const float v0 = acc[mi][ni][rr*2+0], v1 = acc[mi][ni][rr*2+1];
                float2 op = *(const float2*)&outPrev[(size_t)row * OUT_STRIDE + col];
                float2 o;
                o.x = op.x + 0.2f * tanhf(v0 + bias[col]);
                o.y = op.y + 0.2f * tanhf(v1 + bias[col + 1]);
                *(float2*)&C[(size_t)row * OUT_STRIDE + col] = o;
                if (ePtr) *(float2*)&ePtr[(size_t)row * E_STRIDE + col] = o;
                *(float2*)&tfPtr[(size_t)row * ZD + col] = make_float2(rtf(o.x), rtf(o.y));
            }
        }
    }
}

// ---------------------------------------------------------------------------
// fc GEMM (NF=8): EPI 1 = round_tf(relu(acc+bias)), 2 = acc+bias
// ---------------------------------------------------------------------------
template<int EPI>
__global__ __launch_bounds__(256) void fc_gemm(
    const float* __restrict__ A, int lda, int K,
    const float* __restrict__ B, int ldb,
    const float* __restrict__ bias,
    float* __restrict__ C, int ldc)
{
    extern __shared__ uint32_t sm[];
    const uint32_t smBase = smem_u32(sm);
    const int tid = threadIdx.x;
    const int wid = tid >> 5, lane = tid & 31;
    const int grp = lane >> 2, tig = lane & 3;
    const int wm  = (wid >> 1) * 32;
    const int wn  = (wid & 1) * 64;
    const int bm  = blockIdx.y * 128;
    const int bn  = blockIdx.x * 128;

    float acc[2][8][4];
    run_gemm<8>(acc, A, lda, K, nullptr, 0, 0, B, ldb, nullptr, 0, bm, bn, smBase);

#pragma unroll
    for (int mi = 0; mi < 2; mi++) {
        const int r0 = bm + wm + mi * 16 + grp;
#pragma unroll
        for (int ni = 0; ni < 8; ni++) {
            const int col = bn + wn + ni * 8 + 2 * tig;
#pragma unroll
            for (int rr = 0; rr < 2; rr++) {
                const int row = r0 + rr * 8;
                float v0 = acc[mi][ni][rr*2+0] + bias[col];
                float v1 = acc[mi][ni][rr*2+1] + bias[col + 1];
                if (EPI == 1) {
                    v0 = rtf(fmaxf(v0, 0.f));
                    v1 = rtf(fmaxf(v1, 0.f));
                }
                *(float2*)&C[(size_t)row * ldc + col] = make_float2(v0, v1);
            }
        }
    }
}

// ---------------------------------------------------------------------------
// Consolidated setup (2 kernels so ncu's -s 5 lands on a gates GEMM)
// ---------------------------------------------------------------------------
// setup1: gate-interleave permutations of the three LSTM weight matrices.
__global__ void setup1(const float* __restrict__ WihEnc, const float* __restrict__ Wih,
                       const float* __restrict__ Whh,
                       float* __restrict__ dEnc, float* __restrict__ dIh,
                       float* __restrict__ dHh)
{
    int idx = blockIdx.x * blockDim.x + threadIdx.x;
    const int N1 = G4 * ZD;           // WihEnc
    const int N2 = 2 * N1;            // + Wih
    const int N3 = N2 + G4 * HD;      // + Whh
    const float* src; float* dst; int K, off;
    if (idx < N1)      { src = WihEnc; dst = dEnc; K = ZD; off = idx; }
    else if (idx < N2) { src = Wih;    dst = dIh;  K = ZD; off = idx - N1; }
    else if (idx < N3) { src = Whh;    dst = dHh;  K = HD; off = idx - N2; }
    else return;
    int P = off / K, k = off - P * K;
    int W = P / 96, r = P - W * 96;
    int k8 = r >> 3, t = (r >> 1) & 3, b2 = r & 1;
    int v = k8 >> 2, g = k8 & 3;
    int j = 24 * W + 6 * t + 3 * b2 + v;
    dst[off] = rtf(src[(size_t)(g * HD + j) * K + k]);
}

// setup2: out/e/outTf init, fc weight rounding, w transpose, bias permutes.
__global__ void setup2(const float* __restrict__ z,
                       float* __restrict__ out, float* __restrict__ e,
                       float* __restrict__ outTf,
                       const float* __restrict__ fc1_w, float* __restrict__ fc1_t,
                       const float* __restrict__ fc2_w, float* __restrict__ fc2_t,
                       const float* __restrict__ w, float* __restrict__ wT,
                       const float* __restrict__ bihE, const float* __restrict__ bhhE,
                       float* __restrict__ bsumEnc,
                       const float* __restrict__ bih, const float* __restrict__ bhh,
                       float* __restrict__ bsum)
{
    int idx = blockIdx.x * blockDim.x + threadIdx.x;
    const int N1 = BN * ZD;
    const int N2 = N1 + ZD * HC_STRIDE;
    const int N3 = N2 + ZD * ZD;
    const int N4 = N3 + ZD * HD;
    const int N5 = N4 + G4;
    const int N6 = N5 + G4;
    if (idx < N1) {
        int b = idx >> 9, n = idx & 511;
        float v = z[idx];
        out[(size_t)b * OUT_STRIDE + n] = v;
        e[(size_t)b * E_STRIDE + n] = v;
        outTf[idx] = rtf(v);
    } else if (idx < N2) {
        int i = idx - N1; fc1_t[i] = rtf(fc1_w[i]);
    } else if (idx < N3) {
        int i = idx - N2; fc2_t[i] = rtf(fc2_w[i]);
    } else if (idx < N4) {
        int i = idx - N3;
        int n = i / HD, k = i - n * HD;
        wT[i] = rtf(w[(size_t)k * ZD + n]);
    } else if (idx < N6) {
        int P = (idx < N5) ? (idx - N4) : (idx - N5);
        int W = P / 96, r = P - W * 96;
        int k8 = r >> 3, t = (r >> 1) & 3, bb = r & 1;
        int v = k8 >> 2, g = k8 & 3;
        int j = 24 * W + 6 * t + 3 * bb + v;
        if (idx < N5) bsumEnc[P] = bihE[g * HD + j] + bhhE[g * HD + j];
        else          bsum[P]    = bih[g * HD + j]  + bhh[g * HD + j];
    }
}

extern "C" void kernel_launch(void* const* d_in, const int* in_sizes, int n_in,
                              void* d_out, int out_size)
{
    (void)in_sizes; (void)n_in; (void)out_size;
    const float* z       = (const float*)d_in[0];
    const float* Wih_enc = (const float*)d_in[1];
    const float* bih_enc = (const float*)d_in[3];
    const float* bhh_enc = (const float*)d_in[4];
    const float* Wih     = (const float*)d_in[5];
    const float* Whh     = (const float*)d_in[6];
    const float* bih     = (const float*)d_in[7];
    const float* bhh     = (const float*)d_in[8];
    const float* w       = (const float*)d_in[9];
    const float* b       = (const float*)d_in[10];
    const float* fc1_w   = (const float*)d_in[11];
    const float* fc1_b   = (const float*)d_in[12];
    const float* fc2_w   = (const float*)d_in[13];
    const float* fc2_b   = (const float*)d_in[14];
    // d_in[2] (Whh_enc) unused: h0 = 0 so the enc Whh term vanishes

    float* out  = (float*)d_out;
    float* e    = out + (size_t)BN * TN * ZD;
    float* erec = e + (size_t)SEQ * ZD;

    float *h0, *h1, *c, *hc, *mid, *outTf;
    float *WihEnc_t, *Wih_t, *Whh_t, *bsumEnc, *bsum, *fc1_t, *fc2_t, *wT;
    cudaGetSymbolAddress((void**)&h0,       g_h0);
    cudaGetSymbolAddress((void**)&h1,       g_h1);
    cudaGetSymbolAddress((void**)&c,        g_c);
    cudaGetSymbolAddress((void**)&hc,       g_hc);
    cudaGetSymbolAddress((void**)&mid,      g_mid);
    cudaGetSymbolAddress((void**)&outTf,    g_outTf);
    cudaGetSymbolAddress((void**)&WihEnc_t, g_WihEnc_t);
    cudaGetSymbolAddress((void**)&Wih_t,    g_Wih_t);
    cudaGetSymbolAddress((void**)&Whh_t,    g_Whh_t);
    cudaGetSymbolAddress((void**)&bsumEnc,  g_bsumEnc);
    cudaGetSymbolAddress((void**)&bsum,     g_bsum);
    cudaGetSymbolAddress((void**)&fc1_t,    g_fc1_t);
    cudaGetSymbolAddress((void**)&fc2_t,    g_fc2_t);
    cudaGetSymbolAddress((void**)&wT,       g_wT);

    float* hbuf[2] = { h0, h1 };

    constexpr int SMEM12 = 3 * (128 + 192) * LDS * 4;  // 138240
    constexpr int SMEM8  = 3 * (128 + 128) * LDS * 4;  // 110592
    constexpr int SMEM4  = 3 * (128 + 64)  * LDS * 4;  // 82944
    cudaFuncSetAttribute(gates_kernel, cudaFuncAttributeMaxDynamicSharedMemorySize, SMEM12);
    cudaFuncSetAttribute(mul_kernel,   cudaFuncAttributeMaxDynamicSharedMemorySize, SMEM4);
    cudaFuncSetAttribute(fc_gemm<1>,   cudaFuncAttributeMaxDynamicSharedMemorySize, SMEM8);
    cudaFuncSetAttribute(fc_gemm<2>,   cudaFuncAttributeMaxDynamicSharedMemorySize, SMEM8);

    // Setup (2 kernels)
    {
        const int n1 = 2 * G4 * ZD + G4 * HD;
        setup1<<<(n1 + 255) / 256, 256>>>(Wih_enc, Wih, Whh, WihEnc_t, Wih_t, Whh_t);
        const int n2 = BN * ZD + ZD * HC_STRIDE + ZD * ZD + ZD * HD + 2 * G4;
        setup2<<<(n2 + 255) / 256, 256>>>(z, out, e, outTf,
                                          fc1_w, fc1_t, fc2_w, fc2_t, w, wT,
                                          bih_enc, bhh_enc, bsumEnc, bih, bhh, bsum);
    }

    // Encoder: fused GEMM + LSTM cell (h0 = c0 = 0 -> useC=0)
    gates_kernel<<<dim3(G4 / 192, BN / 128), 256, SMEM12>>>(
        outTf, nullptr, WihEnc_t, nullptr, bsumEnc, hbuf[0], c, 0, nullptr, 0);

    // 31 recurrent steps
    for (int k = 0; k < TN - 1; ++k) {
        float* hIn  = hbuf[k & 1];
        float* hNew = hbuf[(k + 1) & 1];
        gates_kernel<<<dim3(G4 / 192, BN / 128), 256, SMEM12>>>(
            outTf, hIn, Wih_t, Whh_t, bsum,
            hNew, c, 1, hc + (size_t)k * HC_STRIDE, (TN - 1) * HC_STRIDE);
        mul_kernel<<<dim3(ZD / 64, BN / 128), 256, SMEM4>>>(
            hNew, wT, b,
            out + (size_t)(k + 1) * ZD,
            out + (size_t)k * ZD,
            (k + 1 <= TN - 2) ? (e + (size_t)(k + 1) * ZD) : nullptr,
            outTf);
    }

    // e_rec = relu(hc @ fc1^T + fc1_b) @ fc2^T + fc2_b
    fc_gemm<1><<<dim3(ZD / 128, SEQ / 128), 256, SMEM8>>>(
        hc, HC_STRIDE, HC_STRIDE, fc1_t, HC_STRIDE, fc1_b, mid, ZD);
    fc_gemm<2><<<dim3(ZD / 128, SEQ / 128), 256, SMEM8>>>(
        mid, ZD, ZD, fc2_t, ZD, fc2_b, erec, ZD);
}

// round 16
// speedup vs baseline: 1.1610x; 1.1610x over previous
#include <cuda_runtime.h>
#include <math.h>
#include <stdint.h>

// Problem constants (fixed shapes)
#define BN 2048
#define ZD 512
#define HD 384
#define TN 32
#define G4 (4*HD)              // 1536
#define OUT_STRIDE (TN*ZD)     // 16384
#define E_STRIDE ((TN-1)*ZD)   // 15872
#define HC_STRIDE (2*HD)       // 768
#define SEQ ((TN-1)*BN)        // 63488

#define LDS 36                 // smem row stride in words (32 + 4 pad)

// Scratch (allocation-free: __device__ globals)
__device__ float g_h0[(size_t)BN*HD];
__device__ float g_h1[(size_t)BN*HD];
__device__ float g_c[(size_t)BN*HD];
__device__ float g_hc[(size_t)SEQ*HC_STRIDE];
__device__ float g_mid[(size_t)SEQ*ZD];
__device__ float g_outTf[(size_t)BN*ZD];
__device__ float g_WihEnc_t[(size_t)G4*ZD];
__device__ float g_Wih_t[(size_t)G4*ZD];
__device__ float g_Whh_t[(size_t)G4*HD];
__device__ float g_bsumEnc[G4];
__device__ float g_bsum[G4];
__device__ float g_fc1_t[(size_t)ZD*HC_STRIDE];
__device__ float g_fc2_t[(size_t)ZD*ZD];
__device__ float g_wT[(size_t)ZD*HD];

__device__ __forceinline__ float sigf(float x) { return 1.0f / (1.0f + __expf(-x)); }

__device__ __forceinline__ uint32_t f2tf(float x) {
    uint32_t r;
    asm("cvt.rna.tf32.f32 %0, %1;" : "=r"(r) : "f"(x));
    return r;
}
__device__ __forceinline__ float rtf(float x) { return __uint_as_float(f2tf(x)); }

__device__ __forceinline__ uint32_t smem_u32(const void* p) {
    uint32_t a;
    asm("{ .reg .u64 t; cvta.to.shared.u64 t, %1; cvt.u32.u64 %0, t; }" : "=r"(a) : "l"(p));
    return a;
}

__device__ __forceinline__ void mma_tf32(
    float* c, uint32_t a0, uint32_t a1, uint32_t a2, uint32_t a3,
    uint32_t b0, uint32_t b1)
{
    asm volatile(
        "mma.sync.aligned.m16n8k8.row.col.f32.tf32.tf32.f32 "
        "{%0,%1,%2,%3}, {%4,%5,%6,%7}, {%8,%9}, {%0,%1,%2,%3};"
        : "+f"(c[0]), "+f"(c[1]), "+f"(c[2]), "+f"(c[3])
        : "r"(a0), "r"(a1), "r"(a2), "r"(a3), "r"(b0), "r"(b1));
}

__device__ __forceinline__ void ldm4(uint32_t* r, uint32_t addr) {
    asm volatile("ldmatrix.sync.aligned.m8n8.x4.shared.b16 {%0,%1,%2,%3}, [%4];"
        : "=r"(r[0]), "=r"(r[1]), "=r"(r[2]), "=r"(r[3]) : "r"(addr));
}

__device__ __forceinline__ void cpa16(uint32_t dst, const void* src) {
    asm volatile("cp.async.ca.shared.global [%0], [%1], 16;" :: "r"(dst), "l"(src));
}

// Issue cp.async for a [ROWS x 32 floats] K-major tile (row stride LDS words).
template<int ROWS, int THREADS>
__device__ __forceinline__ void issue_tile(
    const float* __restrict__ G, int row0, int ld, int k0, uint32_t smemBase, int tid)
{
#pragma unroll
    for (int s = tid; s < ROWS * 8; s += THREADS) {
        const int row = s >> 3, c4 = s & 7;
        cpa16(smemBase + (uint32_t)(row * LDS + c4 * 4) * 4u,
              G + (size_t)(row0 + row) * ld + k0 + c4 * 4);
    }
}

// ---------------------------------------------------------------------------
// GEMM mainloop: tf32 mma.sync, NT, 2-stage cp.async double buffer, ldmatrix.
// Block = 128*WN threads = 4m x WN n-warps. Warp tile 32 x (NF*8).
// Block tile 128 x (WN*NF*8). K chunk 32. Dual-A accumulated.
// Fills acc; caller owns the epilogue.
// ---------------------------------------------------------------------------
template<int NF, int WN>
__device__ __forceinline__ void run_gemm(
    float (&acc)[2][NF][4],
    const float* __restrict__ A1, int lda1, int K1,
    const float* __restrict__ A2, int lda2, int K2,
    const float* __restrict__ B1, int ldb1,
    const float* __restrict__ B2, int ldb2,
    int bm, int bn, uint32_t smBase)
{
    constexpr int THREADS = 128 * WN;
    constexpr int BROWS   = WN * NF * 8;        // B tile rows (= block N)
    constexpr int AW      = 128 * LDS;
    constexpr int TILEW   = (128 + BROWS) * LDS;

    const int tid = threadIdx.x;
    const int wid = tid >> 5, lane = tid & 31;
    const int wm  = (wid / WN) * 32;
    const int wn  = (wid % WN) * (NF * 8);

#pragma unroll
    for (int mi = 0; mi < 2; mi++)
#pragma unroll
        for (int ni = 0; ni < NF; ni++)
#pragma unroll
            for (int j = 0; j < 4; j++) acc[mi][ni][j] = 0.0f;

    const int nch1 = K1 >> 5;
    const int nch  = nch1 + (K2 >> 5);

    auto chunkSrc = [&](int c, const float*& Ap, const float*& Bp,
                        int& la, int& lb, int& k0) {
        if (c < nch1) { Ap = A1; Bp = B1; la = lda1; lb = ldb1; k0 = c << 5; }
        else          { Ap = A2; Bp = B2; la = lda2; lb = ldb2; k0 = (c - nch1) << 5; }
    };

    const int a_r = (lane & 7) + ((lane >> 3) & 1) * 8;
    const int a_c = ((lane >> 4) & 1) * 4;
    const int b_r = ((lane >> 4) & 1) * 8 + (lane & 7);
    const int b_c = ((lane >> 3) & 1) * 4;
    const uint32_t aOfs0 = (uint32_t)((wm + a_r) * LDS + a_c) * 4u;
    const uint32_t aOfs1 = aOfs0 + 16u * LDS * 4u;
    const uint32_t bOfs  = (uint32_t)(AW + (wn + b_r) * LDS + b_c) * 4u;

    {   // prologue: prefetch chunk 0
        const float *Ap, *Bp; int la, lb, k0;
        chunkSrc(0, Ap, Bp, la, lb, k0);
        issue_tile<128, THREADS>(Ap, bm, la, k0, smBase, tid);
        issue_tile<BROWS, THREADS>(Bp, bn, lb, k0, smBase + AW * 4, tid);
        asm volatile("cp.async.commit_group;" ::: "memory");
    }

#pragma unroll 1
    for (int c = 0; c < nch; ++c) {
        const uint32_t pb = smBase + (uint32_t)(c & 1) * TILEW * 4u;
        if (c + 1 < nch) {
            const float *Ap, *Bp; int la, lb, k0;
            chunkSrc(c + 1, Ap, Bp, la, lb, k0);
            const uint32_t nb = smBase + (uint32_t)((c + 1) & 1) * TILEW * 4u;
            issue_tile<128, THREADS>(Ap, bm, la, k0, nb, tid);
            issue_tile<BROWS, THREADS>(Bp, bn, lb, k0, nb + AW * 4, tid);
            asm volatile("cp.async.commit_group;" ::: "memory");
            asm volatile("cp.async.wait_group 1;" ::: "memory");
        } else {
            asm volatile("cp.async.wait_group 0;" ::: "memory");
        }
        __syncthreads();
#pragma unroll
        for (int s = 0; s < 4; s++) {
            uint32_t a[2][4], bf[NF][2];
            ldm4(a[0], pb + aOfs0 + s * 32);
            ldm4(a[1], pb + aOfs1 + s * 32);
#pragma unroll
            for (int j = 0; j < NF / 2; j++) {
                uint32_t t[4];
                ldm4(t, pb + bOfs + (uint32_t)j * (16u * LDS * 4u) + s * 32);
                bf[2*j][0]   = t[0]; bf[2*j][1]   = t[1];
                bf[2*j+1][0] = t[2]; bf[2*j+1][1] = t[3];
            }
#pragma unroll
            for (int mi = 0; mi < 2; mi++)
#pragma unroll
                for (int ni = 0; ni < NF; ni++)
                    mma_tf32(acc[mi][ni], a[mi][0], a[mi][1], a[mi][2], a[mi][3],
                             bf[ni][0], bf[ni][1]);
        }
        __syncthreads();
    }
}

// ---------------------------------------------------------------------------
// Fused gates GEMM + LSTM cell kernel: 512 threads (16 warps, 4m x 4n),
// tile 128 x 192, warp tile 32 x 48 (NF=6).
// Gate interleave: col P = 48*Wq + 8*((4u+g)>>1) + 2t + ((4u+g)&1)
//                  <-> unit j = 12*Wq + 3t + u, gate g.
// ---------------------------------------------------------------------------
__global__ __launch_bounds__(512) void gates_kernel(
    const float* __restrict__ A1, const float* __restrict__ A2,
    const float* __restrict__ B1, const float* __restrict__ B2,
    const float* __restrict__ bias,
    float* __restrict__ hOut, float* __restrict__ cPtr,
    int useC, float* __restrict__ hcRow, int hcStride)
{
    extern __shared__ uint32_t sm[];
    const uint32_t smBase = smem_u32(sm);
    const int tid = threadIdx.x;
    const int wid = tid >> 5, lane = tid & 31;
    const int grp = lane >> 2, tig = lane & 3;
    const int wm  = (wid >> 2) * 32;           // wid / WN, WN=4
    const int bm  = blockIdx.y * 128;
    const int bx  = blockIdx.x;

    float acc[2][6][4];
    run_gemm<6, 4>(acc, A1, ZD, ZD, A2, HD, (A2 ? HD : 0),
                   B1, ZD, B2, HD, bm, bx * 192, smBase);

    const int Wq = bx * 4 + (wid & 3);
    const int jbase = 12 * Wq + 3 * tig;
    float bs[3][4];
#pragma unroll
    for (int u = 0; u < 3; u++)
#pragma unroll
        for (int g = 0; g < 4; g++) {
            const int idx = 4 * u + g;
            bs[u][g] = bias[48 * Wq + 8 * (idx >> 1) + 2 * tig + (idx & 1)];
        }
#pragma unroll
    for (int mi = 0; mi < 2; mi++) {
#pragma unroll
        for (int rr = 0; rr < 2; rr++) {
            const int R = bm + wm + mi * 16 + grp + rr * 8;
#pragma unroll
            for (int u = 0; u < 3; u++) {
                const float gi = acc[mi][(4*u+0)>>1][rr*2 + ((4*u+0)&1)] + bs[u][0];
                const float gf = acc[mi][(4*u+1)>>1][rr*2 + ((4*u+1)&1)] + bs[u][1];
                const float gg = acc[mi][(4*u+2)>>1][rr*2 + ((4*u+2)&1)] + bs[u][2];
                const float go = acc[mi][(4*u+3)>>1][rr*2 + ((4*u+3)&1)] + bs[u][3];
                const int j = jbase + u;
                float cn = sigf(gi) * tanhf(gg);
                if (useC) cn += sigf(gf) * cPtr[(size_t)R * HD + j];
                const float hn = sigf(go) * tanhf(cn);
                cPtr[(size_t)R * HD + j] = cn;
                hOut[(size_t)R * HD + j] = rtf(hn);
                if (hcRow) {
                    hcRow[(size_t)R * hcStride + j]      = rtf(hn);
                    hcRow[(size_t)R * hcStride + HD + j] = rtf(cn);
                }
            }
        }
    }
}

// ---------------------------------------------------------------------------
// mul kernel (256 thr, NF=4, WN=2): out = outPrev + 0.2*tanh(acc+bias);
// writes out (exact), e (exact, optional), outTf (tf32-rounded).
// ---------------------------------------------------------------------------
__global__ __launch_bounds__(256) void mul_kernel(
    const float* __restrict__ H, const float* __restrict__ W,
    const float* __restrict__ bias,
    float* __restrict__ C, const float* __restrict__ outPrev,
    float* __restrict__ ePtr, float* __restrict__ tfPtr)
{
    extern __shared__ uint32_t sm[];
    const uint32_t smBase = smem_u32(sm);
    const int tid = threadIdx.x;
    const int wid = tid >> 5, lane = tid & 31;
    const int grp = lane >> 2, tig = lane & 3;
    const int wm  = (wid >> 1) * 32;
    const int wn  = (wid & 1) * 32;
    const int bm  = blockIdx.y * 128;
    const int bn  = blockIdx.x * 64;

    float acc[2][4][4];
    run_gemm<4, 2>(acc, H, HD, HD, nullptr, 0, 0, W, HD, nullptr, 0, bm, bn, smBase);

#pragma unroll
    for (int mi = 0; mi < 2; mi++) {
        const int r0 = bm + wm + mi * 16 + grp;
#pragma unroll
        for (int ni = 0; ni < 4; ni++) {
            const int col = bn + wn + ni * 8 + 2 * tig;
#pragma unroll
            for (int rr = 0; rr < 2; rr++) {
                const int row = r0 + rr * 8;
                const float v0 = acc[mi][ni][rr*2+0], v1 = acc[mi][ni][rr*2+1];
                float2 op = *(const float2*)&outPrev[(size_t)row * OUT_STRIDE + col];
                float2 o;
                o.x = op.x + 0.2f * tanhf(v0 + bias[col]);
                o.y = op.y + 0.2f * tanhf(v1 + bias[col + 1]);
                *(float2*)&C[(size_t)row * OUT_STRIDE + col] = o;
                if (ePtr) *(float2*)&ePtr[(size_t)row * E_STRIDE + col] = o;
                *(float2*)&tfPtr[(size_t)row * ZD + col] = make_float2(rtf(o.x), rtf(o.y));
            }
        }
    }
}

// ---------------------------------------------------------------------------
// fc GEMM (256 thr, NF=8, WN=2): EPI 1 = round_tf(relu(acc+bias)), 2 = acc+bias
// ---------------------------------------------------------------------------
template<int EPI>
__global__ __launch_bounds__(256) void fc_gemm(
    const float* __restrict__ A, int lda, int K,
    const float* __restrict__ B, int ldb,
    const float* __restrict__ bias,
    float* __restrict__ C, int ldc)
{
    extern __shared__ uint32_t sm[];
    const uint32_t smBase = smem_u32(sm);
    const int tid = threadIdx.x;
    const int wid = tid >> 5, lane = tid & 31;
    const int grp = lane >> 2, tig = lane & 3;
    const int wm  = (wid >> 1) * 32;
    const int wn  = (wid & 1) * 64;
    const int bm  = blockIdx.y * 128;
    const int bn  = blockIdx.x * 128;

    float acc[2][8][4];
    run_gemm<8, 2>(acc, A, lda, K, nullptr, 0, 0, B, ldb, nullptr, 0, bm, bn, smBase);

#pragma unroll
    for (int mi = 0; mi < 2; mi++) {
        const int r0 = bm + wm + mi * 16 + grp;
#pragma unroll
        for (int ni = 0; ni < 8; ni++) {
            const int col = bn + wn + ni * 8 + 2 * tig;
#pragma unroll
            for (int rr = 0; rr < 2; rr++) {
                const int row = r0 + rr * 8;
                float v0 = acc[mi][ni][rr*2+0] + bias[col];
                float v1 = acc[mi][ni][rr*2+1] + bias[col + 1];
                if (EPI == 1) {
                    v0 = rtf(fmaxf(v0, 0.f));
                    v1 = rtf(fmaxf(v1, 0.f));
                }
                *(float2*)&C[(size_t)row * ldc + col] = make_float2(v0, v1);
            }
        }
    }
}

// ---------------------------------------------------------------------------
// Consolidated setup (2 kernels)
// ---------------------------------------------------------------------------
// setup1: gate-interleave permutations of the three LSTM weight matrices.
// P -> (Wq = P/48, r = P%48, ni = r>>3, t = (r>>1)&3, b = r&1,
//       idx = 2*ni + b, u = idx>>2, g = idx&3, j = 12*Wq + 3t + u)
__global__ void setup1(const float* __restrict__ WihEnc, const float* __restrict__ Wih,
                       const float* __restrict__ Whh,
                       float* __restrict__ dEnc, float* __restrict__ dIh,
                       float* __restrict__ dHh)
{
    int idx0 = blockIdx.x * blockDim.x + threadIdx.x;
    const int N1 = G4 * ZD;
    const int N2 = 2 * N1;
    const int N3 = N2 + G4 * HD;
    const float* src; float* dst; int K, off;
    if (idx0 < N1)      { src = WihEnc; dst = dEnc; K = ZD; off = idx0; }
    else if (idx0 < N2) { src = Wih;    dst = dIh;  K = ZD; off = idx0 - N1; }
    else if (idx0 < N3) { src = Whh;    dst = dHh;  K = HD; off = idx0 - N2; }
    else return;
    int P = off / K, k = off - P * K;
    int Wq = P / 48, r = P - Wq * 48;
    int ni = r >> 3, t = (r >> 1) & 3, b2 = r & 1;
    int gi = 2 * ni + b2;
    int u = gi >> 2, g = gi & 3;
    int j = 12 * Wq + 3 * t + u;
    dst[off] = rtf(src[(size_t)(g * HD + j) * K + k]);
}

// setup2: out/e/outTf init, fc weight rounding, w transpose, bias permutes.
__global__ void setup2(const float* __restrict__ z,
                       float* __restrict__ out, float* __restrict__ e,
                       float* __restrict__ outTf,
                       const float* __restrict__ fc1_w, float* __restrict__ fc1_t,
                       const float* __restrict__ fc2_w, float* __restrict__ fc2_t,
                       const float* __restrict__ w, float* __restrict__ wT,
                       const float* __restrict__ bihE, const float* __restrict__ bhhE,
                       float* __restrict__ bsumEnc,
                       const float* __restrict__ bih, const float* __restrict__ bhh,
                       float* __restrict__ bsum)
{
    int idx = blockIdx.x * blockDim.x + threadIdx.x;
    const int N1 = BN * ZD;
    const int N2 = N1 + ZD * HC_STRIDE;
    const int N3 = N2 + ZD * ZD;
    const int N4 = N3 + ZD * HD;
    const int N5 = N4 + G4;
    const int N6 = N5 + G4;
    if (idx < N1) {
        int b = idx >> 9, n = idx & 511;
        float v = z[idx];
        out[(size_t)b * OUT_STRIDE + n] = v;
        e[(size_t)b * E_STRIDE + n] = v;
        outTf[idx] = rtf(v);
    } else if (idx < N2) {
        int i = idx - N1; fc1_t[i] = rtf(fc1_w[i]);
    } else if (idx < N3) {
        int i = idx - N2; fc2_t[i] = rtf(fc2_w[i]);
    } else if (idx < N4) {
        int i = idx - N3;
        int n = i / HD, k = i - n * HD;
        wT[i] = rtf(w[(size_t)k * ZD + n]);
    } else if (idx < N6) {
        int P = (idx < N5) ? (idx - N4) : (idx - N5);
        int Wq = P / 48, r = P - Wq * 48;
        int ni = r >> 3, t = (r >> 1) & 3, b2 = r & 1;
        int gi = 2 * ni + b2;
        int u = gi >> 2, g = gi & 3;
        int j = 12 * Wq + 3 * t + u;
        if (idx < N5) bsumEnc[P] = bihE[g * HD + j] + bhhE[g * HD + j];
        else          bsum[P]    = bih[g * HD + j]  + bhh[g * HD + j];
    }
}

extern "C" void kernel_launch(void* const* d_in, const int* in_sizes, int n_in,
                              void* d_out, int out_size)
{
    (void)in_sizes; (void)n_in; (void)out_size;
    const float* z       = (const float*)d_in[0];
    const float* Wih_enc = (const float*)d_in[1];
    const float* bih_enc = (const float*)d_in[3];
    const float* bhh_enc = (const float*)d_in[4];
    const float* Wih     = (const float*)d_in[5];
    const float* Whh     = (const float*)d_in[6];
    const float* bih     = (const float*)d_in[7];
    const float* bhh     = (const float*)d_in[8];
    const float* w       = (const float*)d_in[9];
    const float* b       = (const float*)d_in[10];
    const float* fc1_w   = (const float*)d_in[11];
    const float* fc1_b   = (const float*)d_in[12];
    const float* fc2_w   = (const float*)d_in[13];
    const float* fc2_b   = (const float*)d_in[14];
    // d_in[2] (Whh_enc) unused: h0 = 0 so the enc Whh term vanishes

    float* out  = (float*)d_out;
    float* e    = out + (size_t)BN * TN * ZD;
    float* erec = e + (size_t)SEQ * ZD;

    float *h0, *h1, *c, *hc, *mid, *outTf;
    float *WihEnc_t, *Wih_t, *Whh_t, *bsumEnc, *bsum, *fc1_t, *fc2_t, *wT;
    cudaGetSymbolAddress((void**)&h0,       g_h0);
    cudaGetSymbolAddress((void**)&h1,       g_h1);
    cudaGetSymbolAddress((void**)&c,        g_c);
    cudaGetSymbolAddress((void**)&hc,       g_hc);
    cudaGetSymbolAddress((void**)&mid,      g_mid);
    cudaGetSymbolAddress((void**)&outTf,    g_outTf);
    cudaGetSymbolAddress((void**)&WihEnc_t, g_WihEnc_t);
    cudaGetSymbolAddress((void**)&Wih_t,    g_Wih_t);
    cudaGetSymbolAddress((void**)&Whh_t,    g_Whh_t);
    cudaGetSymbolAddress((void**)&bsumEnc,  g_bsumEnc);
    cudaGetSymbolAddress((void**)&bsum,     g_bsum);
    cudaGetSymbolAddress((void**)&fc1_t,    g_fc1_t);
    cudaGetSymbolAddress((void**)&fc2_t,    g_fc2_t);
    cudaGetSymbolAddress((void**)&wT,       g_wT);

    float* hbuf[2] = { h0, h1 };

    constexpr int SMEMG = 2 * (128 + 192) * LDS * 4;  // 92160 (gates, 512 thr)
    constexpr int SMEM8 = 2 * (128 + 128) * LDS * 4;  // 73728 (fc)
    constexpr int SMEM4 = 2 * (128 + 64)  * LDS * 4;  // 55296 (mul)
    cudaFuncSetAttribute(gates_kernel, cudaFuncAttributeMaxDynamicSharedMemorySize, SMEMG);
    cudaFuncSetAttribute(mul_kernel,   cudaFuncAttributeMaxDynamicSharedMemorySize, SMEM4);
    cudaFuncSetAttribute(fc_gemm<1>,   cudaFuncAttributeMaxDynamicSharedMemorySize, SMEM8);
    cudaFuncSetAttribute(fc_gemm<2>,   cudaFuncAttributeMaxDynamicSharedMemorySize, SMEM8);

    // Setup (2 kernels)
    {
        const int n1 = 2 * G4 * ZD + G4 * HD;
        setup1<<<(n1 + 255) / 256, 256>>>(Wih_enc, Wih, Whh, WihEnc_t, Wih_t, Whh_t);
        const int n2 = BN * ZD + ZD * HC_STRIDE + ZD * ZD + ZD * HD + 2 * G4;
        setup2<<<(n2 + 255) / 256, 256>>>(z, out, e, outTf,
                                          fc1_w, fc1_t, fc2_w, fc2_t, w, wT,
                                          bih_enc, bhh_enc, bsumEnc, bih, bhh, bsum);
    }

    // Encoder: fused GEMM + LSTM cell (h0 = c0 = 0 -> useC=0)
    gates_kernel<<<dim3(G4 / 192, BN / 128), 512, SMEMG>>>(
        outTf, nullptr, WihEnc_t, nullptr, bsumEnc, hbuf[0], c, 0, nullptr, 0);

    // 31 recurrent steps
    for (int k = 0; k < TN - 1; ++k) {
        float* hIn  = hbuf[k & 1];
        float* hNew = hbuf[(k + 1) & 1];
        gates_kernel<<<dim3(G4 / 192, BN / 128), 512, SMEMG>>>(
            outTf, hIn, Wih_t, Whh_t, bsum,
            hNew, c, 1, hc + (size_t)k * HC_STRIDE, (TN - 1) * HC_STRIDE);
        mul_kernel<<<dim3(ZD / 64, BN / 128), 256, SMEM4>>>(
            hNew, wT, b,
            out + (size_t)(k + 1) * ZD,
            out + (size_t)k * ZD,
            (k + 1 <= TN - 2) ? (e + (size_t)(k + 1) * ZD) : nullptr,
            outTf);
    }

    // e_rec = relu(hc @ fc1^T + fc1_b) @ fc2^T + fc2_b
    fc_gemm<1><<<dim3(ZD / 128, SEQ / 128), 256, SMEM8>>>(
        hc, HC_STRIDE, HC_STRIDE, fc1_t, HC_STRIDE, fc1_b, mid, ZD);
    fc_gemm<2><<<dim3(ZD / 128, SEQ / 128), 256, SMEM8>>>(
        mid, ZD, ZD, fc2_t, ZD, fc2_b, erec, ZD);
}

// round 17
// speedup vs baseline: 1.1669x; 1.0051x over previous
#include <cuda_runtime.h>
#include <math.h>
#include <stdint.h>

// Problem constants (fixed shapes)
#define BN 2048
#define ZD 512
#define HD 384
#define TN 32
#define G4 (4*HD)              // 1536
#define OUT_STRIDE (TN*ZD)     // 16384
#define E_STRIDE ((TN-1)*ZD)   // 15872
#define HC_STRIDE (2*HD)       // 768
#define SEQ ((TN-1)*BN)        // 63488

#define LDS 36                 // smem row stride in words (32 + 4 pad)

// Scratch (allocation-free: __device__ globals)
__device__ float g_h0[(size_t)BN*HD];
__device__ float g_h1[(size_t)BN*HD];
__device__ float g_c[(size_t)BN*HD];
__device__ float g_hc[(size_t)SEQ*HC_STRIDE];
__device__ float g_mid[(size_t)SEQ*ZD];
__device__ float g_outTf[(size_t)BN*ZD];
__device__ float g_WihEnc_t[(size_t)G4*ZD];
__device__ float g_Wih_t[(size_t)G4*ZD];
__device__ float g_Whh_t[(size_t)G4*HD];
__device__ float g_bsumEnc[G4];
__device__ float g_bsum[G4];
__device__ float g_fc1_t[(size_t)ZD*HC_STRIDE];
__device__ float g_fc2_t[(size_t)ZD*ZD];
__device__ float g_wT[(size_t)ZD*HD];

__device__ __forceinline__ float sigf(float x) { return 1.0f / (1.0f + __expf(-x)); }

__device__ __forceinline__ uint32_t f2tf(float x) {
    uint32_t r;
    asm("cvt.rna.tf32.f32 %0, %1;" : "=r"(r) : "f"(x));
    return r;
}
__device__ __forceinline__ float rtf(float x) { return __uint_as_float(f2tf(x)); }

__device__ __forceinline__ uint32_t smem_u32(const void* p) {
    uint32_t a;
    asm("{ .reg .u64 t; cvta.to.shared.u64 t, %1; cvt.u32.u64 %0, t; }" : "=r"(a) : "l"(p));
    return a;
}

__device__ __forceinline__ void mma_tf32(
    float* c, uint32_t a0, uint32_t a1, uint32_t a2, uint32_t a3,
    uint32_t b0, uint32_t b1)
{
    asm volatile(
        "mma.sync.aligned.m16n8k8.row.col.f32.tf32.tf32.f32 "
        "{%0,%1,%2,%3}, {%4,%5,%6,%7}, {%8,%9}, {%0,%1,%2,%3};"
        : "+f"(c[0]), "+f"(c[1]), "+f"(c[2]), "+f"(c[3])
        : "r"(a0), "r"(a1), "r"(a2), "r"(a3), "r"(b0), "r"(b1));
}

__device__ __forceinline__ void ldm4(uint32_t* r, uint32_t addr) {
    asm volatile("ldmatrix.sync.aligned.m8n8.x4.shared.b16 {%0,%1,%2,%3}, [%4];"
        : "=r"(r[0]), "=r"(r[1]), "=r"(r[2]), "=r"(r[3]) : "r"(addr));
}

__device__ __forceinline__ void cpa16(uint32_t dst, const void* src) {
    asm volatile("cp.async.ca.shared.global [%0], [%1], 16;" :: "r"(dst), "l"(src));
}

// Issue cp.async for a [ROWS x 32 floats] K-major tile (row stride LDS words).
template<int ROWS, int THREADS>
__device__ __forceinline__ void issue_tile(
    const float* __restrict__ G, int row0, int ld, int k0, uint32_t smemBase, int tid)
{
#pragma unroll
    for (int s = tid; s < ROWS * 8; s += THREADS) {
        const int row = s >> 3, c4 = s & 7;
        cpa16(smemBase + (uint32_t)(row * LDS + c4 * 4) * 4u,
              G + (size_t)(row0 + row) * ld + k0 + c4 * 4);
    }
}

// ---------------------------------------------------------------------------
// GEMM mainloop: tf32 mma.sync, NT, 2-stage cp.async double buffer, ldmatrix.
// Block = 128*WN... generalized: 4 m-warps x WN n-warps = 32*(4*WN) threads.
// Warp tile 32 x (NF*8). Block tile 128 x (WN*NF*8). K chunk 32. Dual-A.
// Fills acc; caller owns the epilogue.
// ---------------------------------------------------------------------------
template<int NF, int WN>
__device__ __forceinline__ void run_gemm(
    float (&acc)[2][NF][4],
    const float* __restrict__ A1, int lda1, int K1,
    const float* __restrict__ A2, int lda2, int K2,
    const float* __restrict__ B1, int ldb1,
    const float* __restrict__ B2, int ldb2,
    int bm, int bn, uint32_t smBase)
{
    constexpr int THREADS = 128 * WN;
    constexpr int BROWS   = WN * NF * 8;        // B tile rows (= block N)
    constexpr int AW      = 128 * LDS;
    constexpr int TILEW   = (128 + BROWS) * LDS;

    const int tid = threadIdx.x;
    const int wid = tid >> 5, lane = tid & 31;
    const int wm  = (wid / WN) * 32;
    const int wn  = (wid % WN) * (NF * 8);

#pragma unroll
    for (int mi = 0; mi < 2; mi++)
#pragma unroll
        for (int ni = 0; ni < NF; ni++)
#pragma unroll
            for (int j = 0; j < 4; j++) acc[mi][ni][j] = 0.0f;

    const int nch1 = K1 >> 5;
    const int nch  = nch1 + (K2 >> 5);

    auto chunkSrc = [&](int c, const float*& Ap, const float*& Bp,
                        int& la, int& lb, int& k0) {
        if (c < nch1) { Ap = A1; Bp = B1; la = lda1; lb = ldb1; k0 = c << 5; }
        else          { Ap = A2; Bp = B2; la = lda2; lb = ldb2; k0 = (c - nch1) << 5; }
    };

    const int a_r = (lane & 7) + ((lane >> 3) & 1) * 8;
    const int a_c = ((lane >> 4) & 1) * 4;
    const int b_r = ((lane >> 4) & 1) * 8 + (lane & 7);
    const int b_c = ((lane >> 3) & 1) * 4;
    const uint32_t aOfs0 = (uint32_t)((wm + a_r) * LDS + a_c) * 4u;
    const uint32_t aOfs1 = aOfs0 + 16u * LDS * 4u;
    const uint32_t bOfs  = (uint32_t)(AW + (wn + b_r) * LDS + b_c) * 4u;

    {   // prologue: prefetch chunk 0
        const float *Ap, *Bp; int la, lb, k0;
        chunkSrc(0, Ap, Bp, la, lb, k0);
        issue_tile<128, THREADS>(Ap, bm, la, k0, smBase, tid);
        issue_tile<BROWS, THREADS>(Bp, bn, lb, k0, smBase + AW * 4, tid);
        asm volatile("cp.async.commit_group;" ::: "memory");
    }

#pragma unroll 1
    for (int c = 0; c < nch; ++c) {
        const uint32_t pb = smBase + (uint32_t)(c & 1) * TILEW * 4u;
        if (c + 1 < nch) {
            const float *Ap, *Bp; int la, lb, k0;
            chunkSrc(c + 1, Ap, Bp, la, lb, k0);
            const uint32_t nb = smBase + (uint32_t)((c + 1) & 1) * TILEW * 4u;
            issue_tile<128, THREADS>(Ap, bm, la, k0, nb, tid);
            issue_tile<BROWS, THREADS>(Bp, bn, lb, k0, nb + AW * 4, tid);
            asm volatile("cp.async.commit_group;" ::: "memory");
            asm volatile("cp.async.wait_group 1;" ::: "memory");
        } else {
            asm volatile("cp.async.wait_group 0;" ::: "memory");
        }
        __syncthreads();
#pragma unroll
        for (int s = 0; s < 4; s++) {
            uint32_t a[2][4], bf[NF][2];
            ldm4(a[0], pb + aOfs0 + s * 32);
            ldm4(a[1], pb + aOfs1 + s * 32);
#pragma unroll
            for (int j = 0; j < NF / 2; j++) {
                uint32_t t[4];
                ldm4(t, pb + bOfs + (uint32_t)j * (16u * LDS * 4u) + s * 32);
                bf[2*j][0]   = t[0]; bf[2*j][1]   = t[1];
                bf[2*j+1][0] = t[2]; bf[2*j+1][1] = t[3];
            }
#pragma unroll
            for (int mi = 0; mi < 2; mi++)
#pragma unroll
                for (int ni = 0; ni < NF; ni++)
                    mma_tf32(acc[mi][ni], a[mi][0], a[mi][1], a[mi][2], a[mi][3],
                             bf[ni][0], bf[ni][1]);
        }
        __syncthreads();
    }
}

// ---------------------------------------------------------------------------
// Fused gates GEMM + LSTM cell kernel: 256 threads (8 warps, 4m x 2n),
// tile 128 x 96, 2 CTAs/SM, grid (16,16) = 256 CTAs (single wave at occ 2).
// Gate interleave: col P = 48*Wq + 8*((4u+g)>>1) + 2t + ((4u+g)&1)
//                  <-> unit j = 12*Wq + 3t + u, gate g.   (Wq = bx*2 + (wid&1))
// ---------------------------------------------------------------------------
__global__ __launch_bounds__(256, 2) void gates_kernel(
    const float* __restrict__ A1, const float* __restrict__ A2,
    const float* __restrict__ B1, const float* __restrict__ B2,
    const float* __restrict__ bias,
    float* __restrict__ hOut, float* __restrict__ cPtr,
    int useC, float* __restrict__ hcRow, int hcStride)
{
    extern __shared__ uint32_t sm[];
    const uint32_t smBase = smem_u32(sm);
    const int tid = threadIdx.x;
    const int wid = tid >> 5, lane = tid & 31;
    const int grp = lane >> 2, tig = lane & 3;
    const int wm  = (wid >> 1) * 32;           // wid / WN, WN=2
    const int bm  = blockIdx.y * 128;
    const int bx  = blockIdx.x;

    float acc[2][6][4];
    run_gemm<6, 2>(acc, A1, ZD, ZD, A2, HD, (A2 ? HD : 0),
                   B1, ZD, B2, HD, bm, bx * 96, smBase);

    const int Wq = bx * 2 + (wid & 1);
    const int jbase = 12 * Wq + 3 * tig;
    float bs[3][4];
#pragma unroll
    for (int u = 0; u < 3; u++)
#pragma unroll
        for (int g = 0; g < 4; g++) {
            const int idx = 4 * u + g;
            bs[u][g] = bias[48 * Wq + 8 * (idx >> 1) + 2 * tig + (idx & 1)];
        }
#pragma unroll
    for (int mi = 0; mi < 2; mi++) {
#pragma unroll
        for (int rr = 0; rr < 2; rr++) {
            const int R = bm + wm + mi * 16 + grp + rr * 8;
#pragma unroll
            for (int u = 0; u < 3; u++) {
                const float gi = acc[mi][(4*u+0)>>1][rr*2 + ((4*u+0)&1)] + bs[u][0];
                const float gf = acc[mi][(4*u+1)>>1][rr*2 + ((4*u+1)&1)] + bs[u][1];
                const float gg = acc[mi][(4*u+2)>>1][rr*2 + ((4*u+2)&1)] + bs[u][2];
                const float go = acc[mi][(4*u+3)>>1][rr*2 + ((4*u+3)&1)] + bs[u][3];
                const int j = jbase + u;
                float cn = sigf(gi) * tanhf(gg);
                if (useC) cn += sigf(gf) * cPtr[(size_t)R * HD + j];
                const float hn = sigf(go) * tanhf(cn);
                cPtr[(size_t)R * HD + j] = cn;
                hOut[(size_t)R * HD + j] = rtf(hn);
                if (hcRow) {
                    hcRow[(size_t)R * hcStride + j]      = rtf(hn);
                    hcRow[(size_t)R * hcStride + HD + j] = rtf(cn);
                }
            }
        }
    }
}

// ---------------------------------------------------------------------------
// mul kernel (512 thr, 16 warps 4m x 4n, NF=2, tile 128x64):
// out = outPrev + 0.2*tanh(acc+bias); writes out, e (optional), outTf.
// ---------------------------------------------------------------------------
__global__ __launch_bounds__(512) void mul_kernel(
    const float* __restrict__ H, const float* __restrict__ W,
    const float* __restrict__ bias,
    float* __restrict__ C, const float* __restrict__ outPrev,
    float* __restrict__ ePtr, float* __restrict__ tfPtr)
{
    extern __shared__ uint32_t sm[];
    const uint32_t smBase = smem_u32(sm);
    const int tid = threadIdx.x;
    const int wid = tid >> 5, lane = tid & 31;
    const int grp = lane >> 2, tig = lane & 3;
    const int wm  = (wid >> 2) * 32;
    const int wn  = (wid & 3) * 16;
    const int bm  = blockIdx.y * 128;
    const int bn  = blockIdx.x * 64;

    float acc[2][2][4];
    run_gemm<2, 4>(acc, H, HD, HD, nullptr, 0, 0, W, HD, nullptr, 0, bm, bn, smBase);

#pragma unroll
    for (int mi = 0; mi < 2; mi++) {
        const int r0 = bm + wm + mi * 16 + grp;
#pragma unroll
        for (int ni = 0; ni < 2; ni++) {
            const int col = bn + wn + ni * 8 + 2 * tig;
#pragma unroll
            for (int rr = 0; rr < 2; rr++) {
                const int row = r0 + rr * 8;
                const float v0 = acc[mi][ni][rr*2+0], v1 = acc[mi][ni][rr*2+1];
                float2 op = *(const float2*)&outPrev[(size_t)row * OUT_STRIDE + col];
                float2 o;
                o.x = op.x + 0.2f * tanhf(v0 + bias[col]);
                o.y = op.y + 0.2f * tanhf(v1 + bias[col + 1]);
                *(float2*)&C[(size_t)row * OUT_STRIDE + col] = o;
                if (ePtr) *(float2*)&ePtr[(size_t)row * E_STRIDE + col] = o;
                *(float2*)&tfPtr[(size_t)row * ZD + col] = make_float2(rtf(o.x), rtf(o.y));
            }
        }
    }
}

// ---------------------------------------------------------------------------
// fc GEMM (512 thr, 16 warps 4m x 4n, NF=4, tile 128x128):
// EPI 1 = round_tf(relu(acc+bias)), 2 = acc+bias
// ---------------------------------------------------------------------------
template<int EPI>
__global__ __launch_bounds__(512) void fc_gemm(
    const float* __restrict__ A, int lda, int K,
    const float* __restrict__ B, int ldb,
    const float* __restrict__ bias,
    float* __restrict__ C, int ldc)
{
    extern __shared__ uint32_t sm[];
    const uint32_t smBase = smem_u32(sm);
    const int tid = threadIdx.x;
    const int wid = tid >> 5, lane = tid & 31;
    const int grp = lane >> 2, tig = lane & 3;
    const int wm  = (wid >> 2) * 32;
    const int wn  = (wid & 3) * 32;
    const int bm  = blockIdx.y * 128;
    const int bn  = blockIdx.x * 128;

    float acc[2][4][4];
    run_gemm<4, 4>(acc, A, lda, K, nullptr, 0, 0, B, ldb, nullptr, 0, bm, bn, smBase);

#pragma unroll
    for (int mi = 0; mi < 2; mi++) {
        const int r0 = bm + wm + mi * 16 + grp;
#pragma unroll
        for (int ni = 0; ni < 4; ni++) {
            const int col = bn + wn + ni * 8 + 2 * tig;
#pragma unroll
            for (int rr = 0; rr < 2; rr++) {
                const int row = r0 + rr * 8;
                float v0 = acc[mi][ni][rr*2+0] + bias[col];
                float v1 = acc[mi][ni][rr*2+1] + bias[col + 1];
                if (EPI == 1) {
                    v0 = rtf(fmaxf(v0, 0.f));
                    v1 = rtf(fmaxf(v1, 0.f));
                }
                *(float2*)&C[(size_t)row * ldc + col] = make_float2(v0, v1);
            }
        }
    }
}

// ---------------------------------------------------------------------------
// Consolidated setup (2 kernels) — permutation layout UNCHANGED from R16
// ---------------------------------------------------------------------------
__global__ void setup1(const float* __restrict__ WihEnc, const float* __restrict__ Wih,
                       const float* __restrict__ Whh,
                       float* __restrict__ dEnc, float* __restrict__ dIh,
                       float* __restrict__ dHh)
{
    int idx0 = blockIdx.x * blockDim.x + threadIdx.x;
    const int N1 = G4 * ZD;
    const int N2 = 2 * N1;
    const int N3 = N2 + G4 * HD;
    const float* src; float* dst; int K, off;
    if (idx0 < N1)      { src = WihEnc; dst = dEnc; K = ZD; off = idx0; }
    else if (idx0 < N2) { src = Wih;    dst = dIh;  K = ZD; off = idx0 - N1; }
    else if (idx0 < N3) { src = Whh;    dst = dHh;  K = HD; off = idx0 - N2; }
    else return;
    int P = off / K, k = off - P * K;
    int Wq = P / 48, r = P - Wq * 48;
    int ni = r >> 3, t = (r >> 1) & 3, b2 = r & 1;
    int gi = 2 * ni + b2;
    int u = gi >> 2, g = gi & 3;
    int j = 12 * Wq + 3 * t + u;
    dst[off] = rtf(src[(size_t)(g * HD + j) * K + k]);
}

__global__ void setup2(const float* __restrict__ z,
                       float* __restrict__ out, float* __restrict__ e,
                       float* __restrict__ outTf,
                       const float* __restrict__ fc1_w, float* __restrict__ fc1_t,
                       const float* __restrict__ fc2_w, float* __restrict__ fc2_t,
                       const float* __restrict__ w, float* __restrict__ wT,
                       const float* __restrict__ bihE, const float* __restrict__ bhhE,
                       float* __restrict__ bsumEnc,
                       const float* __restrict__ bih, const float* __restrict__ bhh,
                       float* __restrict__ bsum)
{
    int idx = blockIdx.x * blockDim.x + threadIdx.x;
    const int N1 = BN * ZD;
    const int N2 = N1 + ZD * HC_STRIDE;
    const int N3 = N2 + ZD * ZD;
    const int N4 = N3 + ZD * HD;
    const int N5 = N4 + G4;
    const int N6 = N5 + G4;
    if (idx < N1) {
        int b = idx >> 9, n = idx & 511;
        float v = z[idx];
        out[(size_t)b * OUT_STRIDE + n] = v;
        e[(size_t)b * E_STRIDE + n] = v;
        outTf[idx] = rtf(v);
    } else if (idx < N2) {
        int i = idx - N1; fc1_t[i] = rtf(fc1_w[i]);
    } else if (idx < N3) {
        int i = idx - N2; fc2_t[i] = rtf(fc2_w[i]);
    } else if (idx < N4) {
        int i = idx - N3;
        int n = i / HD, k = i - n * HD;
        wT[i] = rtf(w[(size_t)k * ZD + n]);
    } else if (idx < N6) {
        int P = (idx < N5) ? (idx - N4) : (idx - N5);
        int Wq = P / 48, r = P - Wq * 48;
        int ni = r >> 3, t = (r >> 1) & 3, b2 = r & 1;
        int gi = 2 * ni + b2;
        int u = gi >> 2, g = gi & 3;
        int j = 12 * Wq + 3 * t + u;
        if (idx < N5) bsumEnc[P] = bihE[g * HD + j] + bhhE[g * HD + j];
        else          bsum[P]    = bih[g * HD + j]  + bhh[g * HD + j];
    }
}

extern "C" void kernel_launch(void* const* d_in, const int* in_sizes, int n_in,
                              void* d_out, int out_size)
{
    (void)in_sizes; (void)n_in; (void)out_size;
    const float* z       = (const float*)d_in[0];
    const float* Wih_enc = (const float*)d_in[1];
    const float* bih_enc = (const float*)d_in[3];
    const float* bhh_enc = (const float*)d_in[4];
    const float* Wih     = (const float*)d_in[5];
    const float* Whh     = (const float*)d_in[6];
    const float* bih     = (const float*)d_in[7];
    const float* bhh     = (const float*)d_in[8];
    const float* w       = (const float*)d_in[9];
    const float* b       = (const float*)d_in[10];
    const float* fc1_w   = (const float*)d_in[11];
    const float* fc1_b   = (const float*)d_in[12];
    const float* fc2_w   = (const float*)d_in[13];
    const float* fc2_b   = (const float*)d_in[14];
    // d_in[2] (Whh_enc) unused: h0 = 0 so the enc Whh term vanishes

    float* out  = (float*)d_out;
    float* e    = out + (size_t)BN * TN * ZD;
    float* erec = e + (size_t)SEQ * ZD;

    float *h0, *h1, *c, *hc, *mid, *outTf;
    float *WihEnc_t, *Wih_t, *Whh_t, *bsumEnc, *bsum, *fc1_t, *fc2_t, *wT;
    cudaGetSymbolAddress((void**)&h0,       g_h0);
    cudaGetSymbolAddress((void**)&h1,       g_h1);
    cudaGetSymbolAddress((void**)&c,        g_c);
    cudaGetSymbolAddress((void**)&hc,       g_hc);
    cudaGetSymbolAddress((void**)&mid,      g_mid);
    cudaGetSymbolAddress((void**)&outTf,    g_outTf);
    cudaGetSymbolAddress((void**)&WihEnc_t, g_WihEnc_t);
    cudaGetSymbolAddress((void**)&Wih_t,    g_Wih_t);
    cudaGetSymbolAddress((void**)&Whh_t,    g_Whh_t);
    cudaGetSymbolAddress((void**)&bsumEnc,  g_bsumEnc);
    cudaGetSymbolAddress((void**)&bsum,     g_bsum);
    cudaGetSymbolAddress((void**)&fc1_t,    g_fc1_t);
    cudaGetSymbolAddress((void**)&fc2_t,    g_fc2_t);
    cudaGetSymbolAddress((void**)&wT,       g_wT);

    float* hbuf[2] = { h0, h1 };

    constexpr int SMEMG = 2 * (128 + 96)  * LDS * 4;  // 64512 (gates, 256 thr, 2/SM)
    constexpr int SMEM8 = 2 * (128 + 128) * LDS * 4;  // 73728 (fc, 512 thr)
    constexpr int SMEM4 = 2 * (128 + 64)  * LDS * 4;  // 55296 (mul, 512 thr)
    cudaFuncSetAttribute(gates_kernel, cudaFuncAttributeMaxDynamicSharedMemorySize, SMEMG);
    cudaFuncSetAttribute(mul_kernel,   cudaFuncAttributeMaxDynamicSharedMemorySize, SMEM4);
    cudaFuncSetAttribute(fc_gemm<1>,   cudaFuncAttributeMaxDynamicSharedMemorySize, SMEM8);
    cudaFuncSetAttribute(fc_gemm<2>,   cudaFuncAttributeMaxDynamicSharedMemorySize, SMEM8);

    // Setup (2 kernels)
    {
        const int n1 = 2 * G4 * ZD + G4 * HD;
        setup1<<<(n1 + 255) / 256, 256>>>(Wih_enc, Wih, Whh, WihEnc_t, Wih_t, Whh_t);
        const int n2 = BN * ZD + ZD * HC_STRIDE + ZD * ZD + ZD * HD + 2 * G4;
        setup2<<<(n2 + 255) / 256, 256>>>(z, out, e, outTf,
                                          fc1_w, fc1_t, fc2_w, fc2_t, w, wT,
                                          bih_enc, bhh_enc, bsumEnc, bih, bhh, bsum);
    }

    // Encoder: fused GEMM + LSTM cell (h0 = c0 = 0 -> useC=0)
    gates_kernel<<<dim3(G4 / 96, BN / 128), 256, SMEMG>>>(
        outTf, nullptr, WihEnc_t, nullptr, bsumEnc, hbuf[0], c, 0, nullptr, 0);

    // 31 recurrent steps
    for (int k = 0; k < TN - 1; ++k) {
        float* hIn  = hbuf[k & 1];
        float* hNew = hbuf[(k + 1) & 1];
        gates_kernel<<<dim3(G4 / 96, BN / 128), 256, SMEMG>>>(
            outTf, hIn, Wih_t, Whh_t, bsum,
            hNew, c, 1, hc + (size_t)k * HC_STRIDE, (TN - 1) * HC_STRIDE);
        mul_kernel<<<dim3(ZD / 64, BN / 128), 512, SMEM4>>>(
            hNew, wT, b,
            out + (size_t)(k + 1) * ZD,
            out + (size_t)k * ZD,
            (k + 1 <= TN - 2) ? (e + (size_t)(k + 1) * ZD) : nullptr,
            outTf);
    }

    // e_rec = relu(hc @ fc1^T + fc1_b) @ fc2^T + fc2_b
    fc_gemm<1><<<dim3(ZD / 128, SEQ / 128), 512, SMEM8>>>(
        hc, HC_STRIDE, HC_STRIDE, fc1_t, HC_STRIDE, fc1_b, mid, ZD);
    fc_gemm<2><<<dim3(ZD / 128, SEQ / 128), 512, SMEM8>>>(
        mid, ZD, ZD, fc2_t, ZD, fc2_b, erec, ZD);
}